// round 11
// baseline (speedup 1.0000x reference)
#include <cuda_runtime.h>
#include <math.h>

#define B_DIM 64
#define C_DIM 64
#define K_CL 8
#define HW 12544            // floats per plane
#define HF 6272             // floats per half-plane
#define HF4 1568            // float4 per half-plane
#define BC (B_DIM * C_DIM)  // 4096 planes
#define NTH (BC * 2)        // 8192 half-plane tasks
#define EPS 1e-6f
#define NTHR 256

// ---- device scratch -------------------------------------------------------
__device__ int   g_cid[B_DIM];
__device__ float g_lmda[B_DIM];
__device__ int   g_count[K_CL];
__device__ int   g_ntqh[K_CL];         // half-tasks per cluster (= count*128)
__device__ int   g_plane_order[BC];    // planes sorted cluster-major
__device__ int   g_ocid[BC];           // cluster of ordered plane
__device__ float g_q1[BC * 2];         // per-half partial sums
__device__ float g_q2[BC * 2];
__device__ float g_cmu[K_CL * C_DIM];
__device__ float g_cstd[K_CL * C_DIM];
__device__ int   g_curA;               // global A cursor (half-tasks)
__device__ int   g_curC;               // global C cursor (half-tasks)
__device__ int   g_doneA[K_CL];        // completed A half-tasks per cluster
__device__ int   g_cdone[K_CL];        // completed C half-tasks per cluster
__device__ int   g_flag[K_CL];

// ---------------------------------------------------------------------------
// Kernel A: schedule (parallel, 1 block).
// ---------------------------------------------------------------------------
__global__ __launch_bounds__(256) void k_schedule(const float* __restrict__ cluster_map,
                                                  const float* __restrict__ lmda) {
    __shared__ int sh_cid[B_DIM];
    __shared__ int sh_sorted_b[B_DIM];
    __shared__ int sh_off[K_CL];
    __shared__ int sh_cnt[K_CL];

    const int tid = threadIdx.x;

    if (tid < B_DIM) {
        const float* row = cluster_map + tid * K_CL;
        float best = row[0];
        int bi = 0;
#pragma unroll
        for (int k = 1; k < K_CL; ++k) {
            float v = row[k];
            if (v > best) { best = v; bi = k; }
        }
        sh_cid[tid] = bi;
        g_cid[tid] = bi;
        g_lmda[tid] = lmda[tid];
    }
    __syncthreads();

    if (tid < K_CL) {
        int c = 0;
#pragma unroll
        for (int b = 0; b < B_DIM; ++b) c += (sh_cid[b] == tid);
        sh_cnt[tid] = c;
        g_count[tid] = c;
        g_ntqh[tid] = c * C_DIM * 2;
        g_doneA[tid] = 0;
        g_cdone[tid] = 0;
        g_flag[tid] = (c == 0) ? 1 : 0;
    }
    __syncthreads();

    if (tid == 0) {
        int acc = 0;
#pragma unroll
        for (int k = 0; k < K_CL; ++k) { sh_off[k] = acc; acc += sh_cnt[k]; }
        g_curA = 0;
        g_curC = 0;
    }
    __syncthreads();

    if (tid < K_CL) {
        int pos = sh_off[tid];
#pragma unroll
        for (int b = 0; b < B_DIM; ++b)
            if (sh_cid[b] == tid) sh_sorted_b[pos++] = b;
    }
    __syncthreads();

    for (int i = tid; i < BC; i += 256) {
        int b = sh_sorted_b[i >> 6];
        g_plane_order[i] = b * C_DIM + (i & 63);
        g_ocid[i] = sh_cid[b];
    }
}

// ---------------------------------------------------------------------------
// C loop: pure apply streamer (callable by C-blocks and retired A-blocks).
// ---------------------------------------------------------------------------
__device__ void c_loop(const float* __restrict__ x, float* __restrict__ out,
                       int* sh_t) {
    const int tid = threadIdx.x;
    for (;;) {
        if (tid == 0) *sh_t = atomicAdd(&g_curC, 1);
        __syncthreads();
        const int t = *sh_t;
        if (t >= NTH) break;

        const int pidx = t >> 1;
        const int h = t & 1;
        const int k = g_ocid[pidx];
        const int plane = g_plane_order[pidx];

        if (tid == 0) {
            while (!(*(volatile int*)&g_flag[k])) __nanosleep(64);
        }
        __syncthreads();

        // per-thread affine (uniform loads — broadcast, no barrier needed)
        const int b = plane >> 6;
        const int c = plane & 63;
        float s1 = __ldcg(&g_q1[plane * 2]) + __ldcg(&g_q1[plane * 2 + 1]);
        float s2 = __ldcg(&g_q2[plane * 2]) + __ldcg(&g_q2[plane * 2 + 1]);
        float smu = s1 * (1.0f / (float)HW);
        float svar = (s2 - (float)HW * smu * smu) * (1.0f / (float)(HW - 1));
        float sstd = sqrtf(svar + EPS);
        float cmu = __ldcg(&g_cmu[k * C_DIM + c]);
        float cstd = __ldcg(&g_cstd[k * C_DIM + c]);
        float l = g_lmda[b];
        float std_mix = sstd * l + cstd * (1.0f - l);
        float mu_mix = smu * l + cmu * (1.0f - l);
        float scale = std_mix / sstd;
        float bias = mu_mix - smu * scale;

        const float4* __restrict__ px =
            reinterpret_cast<const float4*>(x + (size_t)plane * HW + h * HF);
        float4* __restrict__ po =
            reinterpret_cast<float4*>(out + (size_t)plane * HW + h * HF);
#pragma unroll 4
        for (int i = tid; i < HF4; i += NTHR) {
            float4 v = __ldcs(&px[i]);   // L2-hot; dead after this read
            v.x = fmaf(v.x, scale, bias);
            v.y = fmaf(v.y, scale, bias);
            v.z = fmaf(v.z, scale, bias);
            v.w = fmaf(v.w, scale, bias);
            __stcs(&po[i], v);           // streaming store
        }
        __syncthreads();                 // all stores issued before counting
        if (tid == 0) atomicAdd(&g_cdone[k], 1);
        __syncthreads();                 // protect sh_t for next dequeue
    }
}

// ---------------------------------------------------------------------------
// Kernel B: role-split persistent kernel.
// ---------------------------------------------------------------------------
__global__ __launch_bounds__(NTHR, 8) void k_main(const float* __restrict__ x,
                                                  float* __restrict__ out,
                                                  int nA_blocks) {
    __shared__ float r1[8], r2[8];
    __shared__ float scs1[NTHR], scs2[NTHR];
    __shared__ int sh_t, sh_fin;

    const int tid = threadIdx.x;
    const int lane = tid & 31;
    const int wid = tid >> 5;

    if ((int)blockIdx.x < nA_blocks) {
        // ======================= A role: reduce streamer =======================
        for (;;) {
            if (tid == 0) sh_t = atomicAdd(&g_curA, 1);
            __syncthreads();
            const int t = sh_t;
            if (t >= NTH) break;

            const int pidx = t >> 1;
            const int h = t & 1;
            const int k = g_ocid[pidx];
            const int plane = g_plane_order[pidx];

            // throttle: stay within 2 clusters of the apply frontier
            if (k >= 2) {
                if (tid == 0) {
                    const int need = g_ntqh[k - 2];
                    while (*(volatile int*)&g_cdone[k - 2] < need) __nanosleep(128);
                }
                __syncthreads();
            }

            const float4* __restrict__ px =
                reinterpret_cast<const float4*>(x + (size_t)plane * HW + h * HF);
            float s1 = 0.f, s2 = 0.f;
#pragma unroll 4
            for (int i = tid; i < HF4; i += NTHR) {
                float4 v = px[i];   // evict-normal: stays in L2 for C
                s1 += (v.x + v.y) + (v.z + v.w);
                s2 += (v.x * v.x + v.y * v.y) + (v.z * v.z + v.w * v.w);
            }
#pragma unroll
            for (int off = 16; off > 0; off >>= 1) {
                s1 += __shfl_down_sync(0xffffffffu, s1, off);
                s2 += __shfl_down_sync(0xffffffffu, s2, off);
            }
            if (lane == 0) { r1[wid] = s1; r2[wid] = s2; }
            __syncthreads();
            if (tid == 0) {
                float t1 = ((r1[0] + r1[1]) + (r1[2] + r1[3])) +
                           ((r1[4] + r1[5]) + (r1[6] + r1[7]));
                float t2 = ((r2[0] + r2[1]) + (r2[2] + r2[3])) +
                           ((r2[4] + r2[5]) + (r2[6] + r2[7]));
                g_q1[plane * 2 + h] = t1;
                g_q2[plane * 2 + h] = t2;
                __threadfence();   // publish partials before done-count
                sh_fin = (atomicAdd(&g_doneA[k], 1) == g_ntqh[k] - 1);
            }
            __syncthreads();

            if (sh_fin) {
                // ---- finisher: cluster stats (256-thread parallel) ----
                __threadfence();   // acquire: all partials visible
                const int c = tid & 63;
                const int grp = tid >> 6;   // 0..3 -> 16 samples each
                float cs1 = 0.f, cs2 = 0.f;
#pragma unroll
                for (int bb = 0; bb < 16; ++bb) {
                    int b = grp * 16 + bb;
                    if (g_cid[b] == k) {
                        int base = (b * C_DIM + c) * 2;
                        cs1 += __ldcg(&g_q1[base]) + __ldcg(&g_q1[base + 1]);
                        cs2 += __ldcg(&g_q2[base]) + __ldcg(&g_q2[base + 1]);
                    }
                }
                scs1[tid] = cs1;
                scs2[tid] = cs2;
                __syncthreads();
                if (tid < C_DIM) {
                    float t1 = (scs1[tid] + scs1[tid + 64]) +
                               (scs1[tid + 128] + scs1[tid + 192]);
                    float t2 = (scs2[tid] + scs2[tid + 64]) +
                               (scs2[tid + 128] + scs2[tid + 192]);
                    float n_k = fmaxf((float)g_count[k] * (float)HW, 1.0f);
                    float cmu = t1 / n_k;
                    float cvar = (t2 - n_k * cmu * cmu) / fmaxf(n_k - 1.0f, 1.0f);
                    g_cmu[k * C_DIM + tid] = cmu;
                    g_cstd[k * C_DIM + tid] = sqrtf(cvar + EPS);
                    __threadfence();   // publish stats before flag
                }
                __syncthreads();
                if (tid == 0) atomicExch(&g_flag[k], 1);
                __syncthreads();
            }
        }
        // A work exhausted: help drain the apply stream (kills the tail)
        c_loop(x, out, &sh_t);
    } else {
        // ======================= C role: apply streamer =======================
        c_loop(x, out, &sh_t);
    }
}

extern "C" void kernel_launch(void* const* d_in, const int* in_sizes, int n_in,
                              void* d_out, int out_size) {
    const float* x = (const float*)d_in[0];            // [64,64,112,112]
    const float* cluster_map = (const float*)d_in[1];  // [1,64,8]
    const float* lmda = (const float*)d_in[2];         // [64,1,1,1]
    float* out = (float*)d_out;

    int dev = 0, sms = 148;
    cudaGetDevice(&dev);
    cudaDeviceGetAttribute(&sms, cudaDevAttrMultiProcessorCount, dev);
    if (sms < 1) sms = 148;
    int occ = 8;
    cudaOccupancyMaxActiveBlocksPerMultiprocessor(&occ, k_main, NTHR, 0);
    if (occ < 1) occ = 1;
    if (occ > 8) occ = 8;
    const int nb = occ * sms;            // exactly one resident wave
    const int nA = (nb * 45) / 100;      // 45% reduce, 55% apply

    k_schedule<<<1, 256>>>(cluster_map, lmda);
    k_main<<<nb, NTHR>>>(x, out, nA);
}

// round 12
// speedup vs baseline: 1.2606x; 1.2606x over previous
#include <cuda_runtime.h>
#include <math.h>

#define B_DIM 64
#define C_DIM 64
#define K_CL 8
#define HW 12544            // 112*112
#define HW4 3136            // HW/4
#define BC (B_DIM * C_DIM)  // 4096
#define EPS 1e-6f

// Scratch (device globals — no allocation allowed)
__device__ float g_s1[BC];
__device__ float g_s2[BC];
__device__ float g_scale[BC];
__device__ float g_bias[BC];
__device__ int   g_nfin = 0;   // finisher counter (self-resetting)

// ---------------------------------------------------------------------------
// Kernel 1: per-(b,c) plane moments; the LAST block also computes all stats
// (argmax, cluster segment sums, fused per-plane scale/bias).
// ---------------------------------------------------------------------------
__global__ __launch_bounds__(256) void k_moments_stats(const float* __restrict__ x,
                                                       const float* __restrict__ cluster_map,
                                                       const float* __restrict__ lmda) {
    const int bc = blockIdx.x;
    const int tid = threadIdx.x;
    const int lane = tid & 31;
    const int wid = tid >> 5;

    // ---------------- moments for this plane (identical to R2) ----------------
    {
        const float4* __restrict__ p =
            reinterpret_cast<const float4*>(x + (size_t)bc * HW);
        float s1 = 0.f, s2 = 0.f;
#pragma unroll 4
        for (int i = tid; i < HW4; i += 256) {
            float4 v = p[i];              // evict-normal: tail persists for apply
            s1 += (v.x + v.y) + (v.z + v.w);
            s2 += (v.x * v.x + v.y * v.y) + (v.z * v.z + v.w * v.w);
        }
#pragma unroll
        for (int off = 16; off > 0; off >>= 1) {
            s1 += __shfl_down_sync(0xffffffffu, s1, off);
            s2 += __shfl_down_sync(0xffffffffu, s2, off);
        }
        __shared__ float sh1[8], sh2[8];
        if (lane == 0) { sh1[wid] = s1; sh2[wid] = s2; }
        __syncthreads();
        if (wid == 0) {
            s1 = (lane < 8) ? sh1[lane] : 0.f;
            s2 = (lane < 8) ? sh2[lane] : 0.f;
#pragma unroll
            for (int off = 4; off > 0; off >>= 1) {
                s1 += __shfl_down_sync(0xffffffffu, s1, off);
                s2 += __shfl_down_sync(0xffffffffu, s2, off);
            }
            if (lane == 0) { g_s1[bc] = s1; g_s2[bc] = s2; }
        }
    }

    // ---------------- finisher election ----------------
    __shared__ int sh_fin;
    __syncthreads();
    if (tid == 0) {
        __threadfence();                         // publish s1/s2 before count
        sh_fin = (atomicAdd(&g_nfin, 1) == BC - 1);
    }
    __syncthreads();
    if (!sh_fin) return;

    // ================= finisher: the whole stats computation =================
    __threadfence();                             // acquire: all blocks' s1/s2

    __shared__ float sh_s1[BC];
    __shared__ float sh_s2[BC];
    __shared__ float sh_cmu[K_CL * C_DIM];
    __shared__ float sh_cstd[K_CL * C_DIM];
    __shared__ float sh_lmda[B_DIM];
    __shared__ int   sh_cid[B_DIM];
    __shared__ float sh_cnt[K_CL];

    if (tid < B_DIM) {
        const float* row = cluster_map + tid * K_CL;
        float best = row[0];
        int bi = 0;
#pragma unroll
        for (int k = 1; k < K_CL; ++k) {
            float v = row[k];
            if (v > best) { best = v; bi = k; }
        }
        sh_cid[tid] = bi;
        sh_lmda[tid] = lmda[tid];
    }

    for (int i = tid; i < BC; i += 256) {
        sh_s1[i] = __ldcg(&g_s1[i]);
        sh_s2[i] = __ldcg(&g_s2[i]);
    }
    __syncthreads();

    if (tid < K_CL) {
        float c = 0.f;
#pragma unroll
        for (int b = 0; b < B_DIM; ++b)
            if (sh_cid[b] == tid) c += 1.f;
        sh_cnt[tid] = c;
    }
    __syncthreads();

    // cluster stats: one thread per (k,c), deterministic b-order sums
    for (int kc = tid; kc < K_CL * C_DIM; kc += 256) {
        const int k = kc >> 6;
        const int c = kc & 63;
        float cs1 = 0.f, cs2 = 0.f;
#pragma unroll
        for (int b = 0; b < B_DIM; ++b) {
            if (sh_cid[b] == k) {
                cs1 += sh_s1[b * C_DIM + c];
                cs2 += sh_s2[b * C_DIM + c];
            }
        }
        float n_k = fmaxf(sh_cnt[k] * (float)HW, 1.0f);
        float mu = cs1 / n_k;
        float var = (cs2 - n_k * mu * mu) / fmaxf(n_k - 1.0f, 1.0f);
        sh_cmu[kc] = mu;
        sh_cstd[kc] = sqrtf(var + EPS);
    }
    __syncthreads();

    // fused per-plane affine parameters
    const float inv_n = 1.0f / (float)HW;
    const float inv_nm1 = 1.0f / (float)(HW - 1);
    for (int i = tid; i < BC; i += 256) {
        const int b = i >> 6;
        const int c = i & 63;
        float smu = sh_s1[i] * inv_n;
        float svar = (sh_s2[i] - (float)HW * smu * smu) * inv_nm1;
        float sstd = sqrtf(svar + EPS);
        const int k = sh_cid[b];
        float cmu = sh_cmu[k * C_DIM + c];
        float cstd = sh_cstd[k * C_DIM + c];
        float l = sh_lmda[b];
        float std_mix = sstd * l + cstd * (1.0f - l);
        float mu_mix = smu * l + cmu * (1.0f - l);
        float scale = std_mix / sstd;
        g_scale[i] = scale;
        g_bias[i] = mu_mix - smu * scale;
    }

    if (tid == 0) g_nfin = 0;   // reset for next graph replay
}

// ---------------------------------------------------------------------------
// Kernel 2: out = x * scale[bc] + bias[bc]. Identical to R2's k_apply:
// reverse plane order (L2 tail reuse) + streaming stores.
// ---------------------------------------------------------------------------
__global__ __launch_bounds__(256) void k_apply(const float* __restrict__ x,
                                               float* __restrict__ out) {
    const int bc = (BC - 1) - blockIdx.x;   // reverse order for L2 tail reuse
    const float scale = g_scale[bc];
    const float bias = g_bias[bc];
    const float4* __restrict__ px =
        reinterpret_cast<const float4*>(x + (size_t)bc * HW);
    float4* __restrict__ po = reinterpret_cast<float4*>(out + (size_t)bc * HW);

#pragma unroll 4
    for (int i = threadIdx.x; i < HW4; i += 256) {
        float4 v = px[i];
        v.x = fmaf(v.x, scale, bias);
        v.y = fmaf(v.y, scale, bias);
        v.z = fmaf(v.z, scale, bias);
        v.w = fmaf(v.w, scale, bias);
        __stcs(&po[i], v);   // streaming store: don't pollute L2
    }
}

extern "C" void kernel_launch(void* const* d_in, const int* in_sizes, int n_in,
                              void* d_out, int out_size) {
    const float* x = (const float*)d_in[0];            // [64,64,112,112]
    const float* cluster_map = (const float*)d_in[1];  // [1,64,8]
    const float* lmda = (const float*)d_in[2];         // [64,1,1,1]
    float* out = (float*)d_out;

    k_moments_stats<<<BC, 256>>>(x, cluster_map, lmda);
    k_apply<<<BC, 256>>>(x, out);
}

// round 13
// speedup vs baseline: 1.2832x; 1.0179x over previous
#include <cuda_runtime.h>
#include <math.h>

#define B_DIM 64
#define C_DIM 64
#define K_CL 8
#define HW 12544            // 112*112
#define HW4 3136            // HW/4
#define BC (B_DIM * C_DIM)  // 4096
#define EPS 1e-6f

// Scratch (device globals — no allocation allowed)
__device__ float g_s1[BC];
__device__ float g_s2[BC];
__device__ float g_scale[BC];
__device__ float g_bias[BC];
__device__ int   g_nfin = 0;   // finisher counter (self-resetting)

// ---------------------------------------------------------------------------
// Kernel 1: per-(b,c) plane moments; the LAST block computes all stats.
// Finisher reads partial sums from global (L2-hot) — smem stays tiny so the
// streaming phase keeps full occupancy.
// ---------------------------------------------------------------------------
__global__ __launch_bounds__(256) void k_moments_stats(const float* __restrict__ x,
                                                       const float* __restrict__ cluster_map,
                                                       const float* __restrict__ lmda) {
    const int bc = blockIdx.x;
    const int tid = threadIdx.x;
    const int lane = tid & 31;
    const int wid = tid >> 5;

    __shared__ float sh1[8], sh2[8];
    __shared__ int sh_fin;

    // ---------------- moments for this plane (identical to R2) ----------------
    {
        const float4* __restrict__ p =
            reinterpret_cast<const float4*>(x + (size_t)bc * HW);
        float s1 = 0.f, s2 = 0.f;
#pragma unroll 4
        for (int i = tid; i < HW4; i += 256) {
            float4 v = p[i];              // evict-normal: tail persists for apply
            s1 += (v.x + v.y) + (v.z + v.w);
            s2 += (v.x * v.x + v.y * v.y) + (v.z * v.z + v.w * v.w);
        }
#pragma unroll
        for (int off = 16; off > 0; off >>= 1) {
            s1 += __shfl_down_sync(0xffffffffu, s1, off);
            s2 += __shfl_down_sync(0xffffffffu, s2, off);
        }
        if (lane == 0) { sh1[wid] = s1; sh2[wid] = s2; }
        __syncthreads();
        if (wid == 0) {
            s1 = (lane < 8) ? sh1[lane] : 0.f;
            s2 = (lane < 8) ? sh2[lane] : 0.f;
#pragma unroll
            for (int off = 4; off > 0; off >>= 1) {
                s1 += __shfl_down_sync(0xffffffffu, s1, off);
                s2 += __shfl_down_sync(0xffffffffu, s2, off);
            }
            if (lane == 0) { g_s1[bc] = s1; g_s2[bc] = s2; }
        }
    }

    // ---------------- finisher election ----------------
    __syncthreads();
    if (tid == 0) {
        __threadfence();                         // publish s1/s2 before count
        sh_fin = (atomicAdd(&g_nfin, 1) == BC - 1);
    }
    __syncthreads();
    if (!sh_fin) return;

    // ================= finisher: stats from GLOBAL partials =================
    __threadfence();                             // acquire: all blocks' s1/s2

    __shared__ float sh_cmu[K_CL * C_DIM];       // 2 KB
    __shared__ float sh_cstd[K_CL * C_DIM];      // 2 KB
    __shared__ float sh_lmda[B_DIM];             // 256 B
    __shared__ int   sh_cid[B_DIM];              // 256 B
    __shared__ float sh_cnt[K_CL];

    if (tid < B_DIM) {
        const float* row = cluster_map + tid * K_CL;
        float best = row[0];
        int bi = 0;
#pragma unroll
        for (int k = 1; k < K_CL; ++k) {
            float v = row[k];
            if (v > best) { best = v; bi = k; }
        }
        sh_cid[tid] = bi;
        sh_lmda[tid] = lmda[tid];
    }
    __syncthreads();

    if (tid < K_CL) {
        float c = 0.f;
#pragma unroll
        for (int b = 0; b < B_DIM; ++b)
            if (sh_cid[b] == tid) c += 1.f;
        sh_cnt[tid] = c;
    }
    __syncthreads();

    // cluster stats: one thread per (k,c); partials read via L2 (just written)
    for (int kc = tid; kc < K_CL * C_DIM; kc += 256) {
        const int k = kc >> 6;
        const int c = kc & 63;
        float cs1 = 0.f, cs2 = 0.f;
#pragma unroll
        for (int b = 0; b < B_DIM; ++b) {
            if (sh_cid[b] == k) {
                cs1 += __ldcg(&g_s1[b * C_DIM + c]);
                cs2 += __ldcg(&g_s2[b * C_DIM + c]);
            }
        }
        float n_k = fmaxf(sh_cnt[k] * (float)HW, 1.0f);
        float mu = cs1 / n_k;
        float var = (cs2 - n_k * mu * mu) / fmaxf(n_k - 1.0f, 1.0f);
        sh_cmu[kc] = mu;
        sh_cstd[kc] = sqrtf(var + EPS);
    }
    __syncthreads();

    // fused per-plane affine parameters
    const float inv_n = 1.0f / (float)HW;
    const float inv_nm1 = 1.0f / (float)(HW - 1);
    for (int i = tid; i < BC; i += 256) {
        const int b = i >> 6;
        const int c = i & 63;
        float s1v = __ldcg(&g_s1[i]);
        float s2v = __ldcg(&g_s2[i]);
        float smu = s1v * inv_n;
        float svar = (s2v - (float)HW * smu * smu) * inv_nm1;
        float sstd = sqrtf(svar + EPS);
        const int k = sh_cid[b];
        float cmu = sh_cmu[k * C_DIM + c];
        float cstd = sh_cstd[k * C_DIM + c];
        float l = sh_lmda[b];
        float std_mix = sstd * l + cstd * (1.0f - l);
        float mu_mix = smu * l + cmu * (1.0f - l);
        float scale = std_mix / sstd;
        g_scale[i] = scale;
        g_bias[i] = mu_mix - smu * scale;
    }

    if (tid == 0) g_nfin = 0;   // reset for next graph replay
}

// ---------------------------------------------------------------------------
// Kernel 2: out = x * scale[bc] + bias[bc]. Reverse plane order (L2 tail
// reuse) + streaming stores. Identical to R12 (measured 58.2us).
// ---------------------------------------------------------------------------
__global__ __launch_bounds__(256) void k_apply(const float* __restrict__ x,
                                               float* __restrict__ out) {
    const int bc = (BC - 1) - blockIdx.x;   // reverse order for L2 tail reuse
    const float scale = g_scale[bc];
    const float bias = g_bias[bc];
    const float4* __restrict__ px =
        reinterpret_cast<const float4*>(x + (size_t)bc * HW);
    float4* __restrict__ po = reinterpret_cast<float4*>(out + (size_t)bc * HW);

#pragma unroll 4
    for (int i = threadIdx.x; i < HW4; i += 256) {
        float4 v = px[i];
        v.x = fmaf(v.x, scale, bias);
        v.y = fmaf(v.y, scale, bias);
        v.z = fmaf(v.z, scale, bias);
        v.w = fmaf(v.w, scale, bias);
        __stcs(&po[i], v);   // streaming store: don't pollute L2
    }
}

extern "C" void kernel_launch(void* const* d_in, const int* in_sizes, int n_in,
                              void* d_out, int out_size) {
    const float* x = (const float*)d_in[0];            // [64,64,112,112]
    const float* cluster_map = (const float*)d_in[1];  // [1,64,8]
    const float* lmda = (const float*)d_in[2];         // [64,1,1,1]
    float* out = (float*)d_out;

    k_moments_stats<<<BC, 256>>>(x, cluster_map, lmda);
    k_apply<<<BC, 256>>>(x, out);
}

// round 14
// speedup vs baseline: 1.3086x; 1.0198x over previous
#include <cuda_runtime.h>
#include <math.h>

#define B_DIM 64
#define C_DIM 64
#define K_CL 8
#define HW 12544            // 112*112
#define HW4 3136            // HW/4
#define BC (B_DIM * C_DIM)  // 4096
#define EPS 1e-6f

// Scratch (device globals — no allocation allowed)
__device__ float g_s1[BC];
__device__ float g_s2[BC];
__device__ float g_scale[BC];
__device__ float g_bias[BC];
__device__ int   g_nfin = 0;   // finisher counter (self-resetting)

// ---------------------------------------------------------------------------
// Kernel 1: per-(b,c) plane moments; the LAST block computes all stats.
// __launch_bounds__(256, 8) caps registers at 32 so the 4096-block streaming
// phase keeps 8 CTA/SM — the finisher may spill, it runs once.
// ---------------------------------------------------------------------------
__global__ __launch_bounds__(256, 8) void k_moments_stats(const float* __restrict__ x,
                                                          const float* __restrict__ cluster_map,
                                                          const float* __restrict__ lmda) {
    const int bc = blockIdx.x;
    const int tid = threadIdx.x;
    const int lane = tid & 31;
    const int wid = tid >> 5;

    __shared__ float sh1[8], sh2[8];
    __shared__ int sh_fin;

    // ---------------- moments for this plane (identical to R2) ----------------
    {
        const float4* __restrict__ p =
            reinterpret_cast<const float4*>(x + (size_t)bc * HW);
        float s1 = 0.f, s2 = 0.f;
#pragma unroll 4
        for (int i = tid; i < HW4; i += 256) {
            float4 v = p[i];              // evict-normal: tail persists for apply
            s1 += (v.x + v.y) + (v.z + v.w);
            s2 += (v.x * v.x + v.y * v.y) + (v.z * v.z + v.w * v.w);
        }
#pragma unroll
        for (int off = 16; off > 0; off >>= 1) {
            s1 += __shfl_down_sync(0xffffffffu, s1, off);
            s2 += __shfl_down_sync(0xffffffffu, s2, off);
        }
        if (lane == 0) { sh1[wid] = s1; sh2[wid] = s2; }
        __syncthreads();
        if (wid == 0) {
            s1 = (lane < 8) ? sh1[lane] : 0.f;
            s2 = (lane < 8) ? sh2[lane] : 0.f;
#pragma unroll
            for (int off = 4; off > 0; off >>= 1) {
                s1 += __shfl_down_sync(0xffffffffu, s1, off);
                s2 += __shfl_down_sync(0xffffffffu, s2, off);
            }
            if (lane == 0) { g_s1[bc] = s1; g_s2[bc] = s2; }
        }
    }

    // ---------------- finisher election ----------------
    __syncthreads();
    if (tid == 0) {
        __threadfence();                         // publish s1/s2 before count
        sh_fin = (atomicAdd(&g_nfin, 1) == BC - 1);
    }
    __syncthreads();
    if (!sh_fin) return;

    // ================= finisher: stats from GLOBAL partials =================
    __threadfence();                             // acquire: all blocks' s1/s2

    __shared__ float sh_cmu[K_CL * C_DIM];       // 2 KB
    __shared__ float sh_cstd[K_CL * C_DIM];      // 2 KB
    __shared__ float sh_lmda[B_DIM];             // 256 B
    __shared__ int   sh_cid[B_DIM];              // 256 B
    __shared__ float sh_cnt[K_CL];

    if (tid < B_DIM) {
        const float* row = cluster_map + tid * K_CL;
        float best = row[0];
        int bi = 0;
#pragma unroll
        for (int k = 1; k < K_CL; ++k) {
            float v = row[k];
            if (v > best) { best = v; bi = k; }
        }
        sh_cid[tid] = bi;
        sh_lmda[tid] = lmda[tid];
    }
    __syncthreads();

    if (tid < K_CL) {
        float c = 0.f;
#pragma unroll
        for (int b = 0; b < B_DIM; ++b)
            if (sh_cid[b] == tid) c += 1.f;
        sh_cnt[tid] = c;
    }
    __syncthreads();

    // cluster stats: one thread per (k,c); partials read via L2 (just written)
    for (int kc = tid; kc < K_CL * C_DIM; kc += 256) {
        const int k = kc >> 6;
        const int c = kc & 63;
        float cs1 = 0.f, cs2 = 0.f;
#pragma unroll
        for (int b = 0; b < B_DIM; ++b) {
            if (sh_cid[b] == k) {
                cs1 += __ldcg(&g_s1[b * C_DIM + c]);
                cs2 += __ldcg(&g_s2[b * C_DIM + c]);
            }
        }
        float n_k = fmaxf(sh_cnt[k] * (float)HW, 1.0f);
        float mu = cs1 / n_k;
        float var = (cs2 - n_k * mu * mu) / fmaxf(n_k - 1.0f, 1.0f);
        sh_cmu[kc] = mu;
        sh_cstd[kc] = sqrtf(var + EPS);
    }
    __syncthreads();

    // fused per-plane affine parameters
    const float inv_n = 1.0f / (float)HW;
    const float inv_nm1 = 1.0f / (float)(HW - 1);
    for (int i = tid; i < BC; i += 256) {
        const int b = i >> 6;
        const int c = i & 63;
        float s1v = __ldcg(&g_s1[i]);
        float s2v = __ldcg(&g_s2[i]);
        float smu = s1v * inv_n;
        float svar = (s2v - (float)HW * smu * smu) * inv_nm1;
        float sstd = sqrtf(svar + EPS);
        const int k = sh_cid[b];
        float cmu = sh_cmu[k * C_DIM + c];
        float cstd = sh_cstd[k * C_DIM + c];
        float l = sh_lmda[b];
        float std_mix = sstd * l + cstd * (1.0f - l);
        float mu_mix = smu * l + cmu * (1.0f - l);
        float scale = std_mix / sstd;
        g_scale[i] = scale;
        g_bias[i] = mu_mix - smu * scale;
    }

    if (tid == 0) g_nfin = 0;   // reset for next graph replay
}

// ---------------------------------------------------------------------------
// Kernel 2: out = x * scale[bc] + bias[bc]. Reverse plane order (L2 tail
// reuse) + streaming stores. Identical to R12/R13 (measured 58.2/58.9us).
// ---------------------------------------------------------------------------
__global__ __launch_bounds__(256, 8) void k_apply(const float* __restrict__ x,
                                                  float* __restrict__ out) {
    const int bc = (BC - 1) - blockIdx.x;   // reverse order for L2 tail reuse
    const float scale = g_scale[bc];
    const float bias = g_bias[bc];
    const float4* __restrict__ px =
        reinterpret_cast<const float4*>(x + (size_t)bc * HW);
    float4* __restrict__ po = reinterpret_cast<float4*>(out + (size_t)bc * HW);

#pragma unroll 4
    for (int i = threadIdx.x; i < HW4; i += 256) {
        float4 v = px[i];
        v.x = fmaf(v.x, scale, bias);
        v.y = fmaf(v.y, scale, bias);
        v.z = fmaf(v.z, scale, bias);
        v.w = fmaf(v.w, scale, bias);
        __stcs(&po[i], v);   // streaming store: don't pollute L2
    }
}

extern "C" void kernel_launch(void* const* d_in, const int* in_sizes, int n_in,
                              void* d_out, int out_size) {
    const float* x = (const float*)d_in[0];            // [64,64,112,112]
    const float* cluster_map = (const float*)d_in[1];  // [1,64,8]
    const float* lmda = (const float*)d_in[2];         // [64,1,1,1]
    float* out = (float*)d_out;

    k_moments_stats<<<BC, 256>>>(x, cluster_map, lmda);
    k_apply<<<BC, 256>>>(x, out);
}

// round 15
// speedup vs baseline: 1.4458x; 1.1048x over previous
#include <cuda_runtime.h>
#include <math.h>

#define B_DIM 64
#define C_DIM 64
#define K_CL 8
#define HW 12544            // 112*112
#define HW4 3136            // HW/4
#define BC (B_DIM * C_DIM)  // 4096
#define EPS 1e-6f

// Scratch (device globals — no allocation allowed)
__device__ float g_s1[BC];
__device__ float g_s2[BC];
__device__ float g_scale[BC];
__device__ float g_bias[BC];

// ---------------------------------------------------------------------------
// Kernel 1: per-(b,c) plane moments. EXACT copy of R2's kernel (35.6us).
// ---------------------------------------------------------------------------
__global__ __launch_bounds__(256) void k_moments(const float* __restrict__ x) {
    const int bc = blockIdx.x;
    const float4* __restrict__ p =
        reinterpret_cast<const float4*>(x + (size_t)bc * HW);

    float s1 = 0.f, s2 = 0.f;
#pragma unroll 4
    for (int i = threadIdx.x; i < HW4; i += 256) {
        float4 v = p[i];
        s1 += (v.x + v.y) + (v.z + v.w);
        s2 += (v.x * v.x + v.y * v.y) + (v.z * v.z + v.w * v.w);
    }

#pragma unroll
    for (int off = 16; off > 0; off >>= 1) {
        s1 += __shfl_down_sync(0xffffffffu, s1, off);
        s2 += __shfl_down_sync(0xffffffffu, s2, off);
    }

    __shared__ float sh1[8], sh2[8];
    const int lane = threadIdx.x & 31;
    const int wid = threadIdx.x >> 5;
    if (lane == 0) { sh1[wid] = s1; sh2[wid] = s2; }
    __syncthreads();
    if (wid == 0) {
        s1 = (lane < 8) ? sh1[lane] : 0.f;
        s2 = (lane < 8) ? sh2[lane] : 0.f;
#pragma unroll
        for (int off = 4; off > 0; off >>= 1) {
            s1 += __shfl_down_sync(0xffffffffu, s1, off);
            s2 += __shfl_down_sync(0xffffffffu, s2, off);
        }
        if (lane == 0) { g_s1[bc] = s1; g_s2[bc] = s2; }
    }
}

// ---------------------------------------------------------------------------
// Kernel 2: stats, 64 blocks x 64 threads — block c handles channel c.
// Each block: argmax cid (redundant, 2KB L2-hot), its channel's 64 partials,
// 8 cluster stats, 64 fused scale/bias.
// ---------------------------------------------------------------------------
__global__ __launch_bounds__(64) void k_stats(const float* __restrict__ cluster_map,
                                              const float* __restrict__ lmda) {
    const int c = blockIdx.x;       // channel
    const int tid = threadIdx.x;    // sample b

    __shared__ int   sh_cid[B_DIM];
    __shared__ float sh_lmda[B_DIM];
    __shared__ float sh_s1[B_DIM];  // partials for this channel, by sample
    __shared__ float sh_s2[B_DIM];
    __shared__ float sh_cmu[K_CL];
    __shared__ float sh_cstd[K_CL];

    // argmax cid for sample tid + lmda + this channel's partials
    {
        const float* row = cluster_map + tid * K_CL;
        float best = row[0];
        int bi = 0;
#pragma unroll
        for (int k = 1; k < K_CL; ++k) {
            float v = row[k];
            if (v > best) { best = v; bi = k; }
        }
        sh_cid[tid] = bi;
        sh_lmda[tid] = lmda[tid];
        sh_s1[tid] = g_s1[tid * C_DIM + c];
        sh_s2[tid] = g_s2[tid * C_DIM + c];
    }
    __syncthreads();

    // cluster stats for (k, c), k = tid < 8 (deterministic b-order)
    if (tid < K_CL) {
        float cs1 = 0.f, cs2 = 0.f, cnt = 0.f;
#pragma unroll
        for (int b = 0; b < B_DIM; ++b) {
            if (sh_cid[b] == tid) {
                cs1 += sh_s1[b];
                cs2 += sh_s2[b];
                cnt += 1.f;
            }
        }
        float n_k = fmaxf(cnt * (float)HW, 1.0f);
        float mu = cs1 / n_k;
        float var = (cs2 - n_k * mu * mu) / fmaxf(n_k - 1.0f, 1.0f);
        sh_cmu[tid] = mu;
        sh_cstd[tid] = sqrtf(var + EPS);
    }
    __syncthreads();

    // fused affine for plane (b = tid, c)
    {
        const float inv_n = 1.0f / (float)HW;
        const float inv_nm1 = 1.0f / (float)(HW - 1);
        float smu = sh_s1[tid] * inv_n;
        float svar = (sh_s2[tid] - (float)HW * smu * smu) * inv_nm1;
        float sstd = sqrtf(svar + EPS);
        const int k = sh_cid[tid];
        float cmu = sh_cmu[k];
        float cstd = sh_cstd[k];
        float l = sh_lmda[tid];
        float std_mix = sstd * l + cstd * (1.0f - l);
        float mu_mix = smu * l + cmu * (1.0f - l);
        float scale = std_mix / sstd;
        const int bc = tid * C_DIM + c;
        g_scale[bc] = scale;
        g_bias[bc] = mu_mix - smu * scale;
    }
}

// ---------------------------------------------------------------------------
// Kernel 3: out = x * scale[bc] + bias[bc]. EXACT copy of R12-R14 apply
// (measured 58.0us): reverse plane order + streaming stores.
// ---------------------------------------------------------------------------
__global__ __launch_bounds__(256) void k_apply(const float* __restrict__ x,
                                               float* __restrict__ out) {
    const int bc = (BC - 1) - blockIdx.x;   // reverse order for L2 tail reuse
    const float scale = g_scale[bc];
    const float bias = g_bias[bc];
    const float4* __restrict__ px =
        reinterpret_cast<const float4*>(x + (size_t)bc * HW);
    float4* __restrict__ po = reinterpret_cast<float4*>(out + (size_t)bc * HW);

#pragma unroll 4
    for (int i = threadIdx.x; i < HW4; i += 256) {
        float4 v = px[i];
        v.x = fmaf(v.x, scale, bias);
        v.y = fmaf(v.y, scale, bias);
        v.z = fmaf(v.z, scale, bias);
        v.w = fmaf(v.w, scale, bias);
        __stcs(&po[i], v);   // streaming store: don't pollute L2
    }
}

extern "C" void kernel_launch(void* const* d_in, const int* in_sizes, int n_in,
                              void* d_out, int out_size) {
    const float* x = (const float*)d_in[0];            // [64,64,112,112]
    const float* cluster_map = (const float*)d_in[1];  // [1,64,8]
    const float* lmda = (const float*)d_in[2];         // [64,1,1,1]
    float* out = (float*)d_out;

    k_moments<<<BC, 256>>>(x);
    k_stats<<<C_DIM, 64>>>(cluster_map, lmda);
    k_apply<<<BC, 256>>>(x, out);
}

// round 16
// speedup vs baseline: 1.4570x; 1.0078x over previous
#include <cuda_runtime.h>
#include <math.h>

#define B_DIM 64
#define C_DIM 64
#define K_CL 8
#define HW 12544            // 112*112
#define HW4 3136            // HW/4
#define BC (B_DIM * C_DIM)  // 4096
#define EPS 1e-6f

// Scratch (device globals — no allocation allowed)
__device__ float g_s1[BC];
__device__ float g_s2[BC];

// ---------------------------------------------------------------------------
// Kernel 1: per-(b,c) plane moments. EXACT copy of R15 (33.6us measured).
// ---------------------------------------------------------------------------
__global__ __launch_bounds__(256) void k_moments(const float* __restrict__ x) {
    const int bc = blockIdx.x;
    const float4* __restrict__ p =
        reinterpret_cast<const float4*>(x + (size_t)bc * HW);

    float s1 = 0.f, s2 = 0.f;
#pragma unroll 4
    for (int i = threadIdx.x; i < HW4; i += 256) {
        float4 v = p[i];
        s1 += (v.x + v.y) + (v.z + v.w);
        s2 += (v.x * v.x + v.y * v.y) + (v.z * v.z + v.w * v.w);
    }

#pragma unroll
    for (int off = 16; off > 0; off >>= 1) {
        s1 += __shfl_down_sync(0xffffffffu, s1, off);
        s2 += __shfl_down_sync(0xffffffffu, s2, off);
    }

    __shared__ float sh1[8], sh2[8];
    const int lane = threadIdx.x & 31;
    const int wid = threadIdx.x >> 5;
    if (lane == 0) { sh1[wid] = s1; sh2[wid] = s2; }
    __syncthreads();
    if (wid == 0) {
        s1 = (lane < 8) ? sh1[lane] : 0.f;
        s2 = (lane < 8) ? sh2[lane] : 0.f;
#pragma unroll
        for (int off = 4; off > 0; off >>= 1) {
            s1 += __shfl_down_sync(0xffffffffu, s1, off);
            s2 += __shfl_down_sync(0xffffffffu, s2, off);
        }
        if (lane == 0) { g_s1[bc] = s1; g_s2[bc] = s2; }
    }
}

// ---------------------------------------------------------------------------
// Kernel 2: apply with self-contained stats prologue.
// Each block recomputes its plane's affine params from L2-hot data
// (cluster_map 2KB + its channel's 64 partials), then streams.
// Reverse plane order (L2 tail reuse) + streaming stores, as measured 58us.
// ---------------------------------------------------------------------------
__global__ __launch_bounds__(256) void k_apply(const float* __restrict__ x,
                                               const float* __restrict__ cluster_map,
                                               const float* __restrict__ lmda,
                                               float* __restrict__ out) {
    const int bc = (BC - 1) - blockIdx.x;   // reverse order for L2 tail reuse
    const int b_own = bc >> 6;
    const int c = bc & 63;
    const int tid = threadIdx.x;

    __shared__ int   sh_cid[B_DIM];
    __shared__ float sh_ps1[B_DIM];
    __shared__ float sh_ps2[B_DIM];
    __shared__ float sh_scale, sh_bias;

    // ---- prologue: compute this plane's scale/bias (all data L2-hot) ----
    if (tid < B_DIM) {
        const float* row = cluster_map + tid * K_CL;
        float best = row[0];
        int bi = 0;
#pragma unroll
        for (int k = 1; k < K_CL; ++k) {
            float v = row[k];
            if (v > best) { best = v; bi = k; }
        }
        sh_cid[tid] = bi;
        sh_ps1[tid] = __ldcg(&g_s1[tid * C_DIM + c]);
        sh_ps2[tid] = __ldcg(&g_s2[tid * C_DIM + c]);
    }
    __syncthreads();

    if (tid == 0) {
        const int kown = sh_cid[b_own];
        float cs1 = 0.f, cs2 = 0.f, cnt = 0.f;
#pragma unroll
        for (int b = 0; b < B_DIM; ++b) {
            if (sh_cid[b] == kown) {
                cs1 += sh_ps1[b];
                cs2 += sh_ps2[b];
                cnt += 1.f;
            }
        }
        float n_k = fmaxf(cnt * (float)HW, 1.0f);
        float cmu = cs1 / n_k;
        float cvar = (cs2 - n_k * cmu * cmu) / fmaxf(n_k - 1.0f, 1.0f);
        float cstd = sqrtf(cvar + EPS);

        float smu = sh_ps1[b_own] * (1.0f / (float)HW);
        float svar = (sh_ps2[b_own] - (float)HW * smu * smu) * (1.0f / (float)(HW - 1));
        float sstd = sqrtf(svar + EPS);
        float l = lmda[b_own];
        float std_mix = sstd * l + cstd * (1.0f - l);
        float mu_mix = smu * l + cmu * (1.0f - l);
        float scale = std_mix / sstd;
        sh_scale = scale;
        sh_bias = mu_mix - smu * scale;
    }
    __syncthreads();

    const float scale = sh_scale;
    const float bias = sh_bias;

    // ---- stream: identical to the measured-58us apply loop ----
    const float4* __restrict__ px =
        reinterpret_cast<const float4*>(x + (size_t)bc * HW);
    float4* __restrict__ po = reinterpret_cast<float4*>(out + (size_t)bc * HW);

#pragma unroll 4
    for (int i = tid; i < HW4; i += 256) {
        float4 v = px[i];
        v.x = fmaf(v.x, scale, bias);
        v.y = fmaf(v.y, scale, bias);
        v.z = fmaf(v.z, scale, bias);
        v.w = fmaf(v.w, scale, bias);
        __stcs(&po[i], v);   // streaming store: don't pollute L2
    }
}

extern "C" void kernel_launch(void* const* d_in, const int* in_sizes, int n_in,
                              void* d_out, int out_size) {
    const float* x = (const float*)d_in[0];            // [64,64,112,112]
    const float* cluster_map = (const float*)d_in[1];  // [1,64,8]
    const float* lmda = (const float*)d_in[2];         // [64,1,1,1]
    float* out = (float*)d_out;

    k_moments<<<BC, 256>>>(x);
    k_apply<<<BC, 256>>>(x, cluster_map, lmda, out);
}

// round 17
// speedup vs baseline: 1.4812x; 1.0166x over previous
#include <cuda_runtime.h>
#include <math.h>

#define B_DIM 64
#define C_DIM 64
#define K_CL 8
#define HW 12544            // 112*112
#define HW4 3136            // HW/4
#define BC (B_DIM * C_DIM)  // 4096
#define EPS 1e-6f

// Scratch (device globals — no allocation allowed)
__device__ float g_s1[BC];
__device__ float g_s2[BC];

// ---------------------------------------------------------------------------
// Kernel 1: per-(b,c) plane moments. EXACT copy of R15 (33.6us measured).
// ---------------------------------------------------------------------------
__global__ __launch_bounds__(256) void k_moments(const float* __restrict__ x) {
    const int bc = blockIdx.x;
    const float4* __restrict__ p =
        reinterpret_cast<const float4*>(x + (size_t)bc * HW);

    float s1 = 0.f, s2 = 0.f;
#pragma unroll 4
    for (int i = threadIdx.x; i < HW4; i += 256) {
        float4 v = p[i];
        s1 += (v.x + v.y) + (v.z + v.w);
        s2 += (v.x * v.x + v.y * v.y) + (v.z * v.z + v.w * v.w);
    }

#pragma unroll
    for (int off = 16; off > 0; off >>= 1) {
        s1 += __shfl_down_sync(0xffffffffu, s1, off);
        s2 += __shfl_down_sync(0xffffffffu, s2, off);
    }

    __shared__ float sh1[8], sh2[8];
    const int lane = threadIdx.x & 31;
    const int wid = threadIdx.x >> 5;
    if (lane == 0) { sh1[wid] = s1; sh2[wid] = s2; }
    __syncthreads();
    if (wid == 0) {
        s1 = (lane < 8) ? sh1[lane] : 0.f;
        s2 = (lane < 8) ? sh2[lane] : 0.f;
#pragma unroll
        for (int off = 4; off > 0; off >>= 1) {
            s1 += __shfl_down_sync(0xffffffffu, s1, off);
            s2 += __shfl_down_sync(0xffffffffu, s2, off);
        }
        if (lane == 0) { g_s1[bc] = s1; g_s2[bc] = s2; }
    }
}

// ---------------------------------------------------------------------------
// Kernel 2: apply with parallel stats prologue.
// Threads 0..63 compute cid/partials; cluster sums via predicated shuffle
// tree (2 warps) instead of a serial tid-0 chain. Then stream (reverse plane
// order + streaming stores).
// ---------------------------------------------------------------------------
__global__ __launch_bounds__(256) void k_apply(const float* __restrict__ x,
                                               const float* __restrict__ cluster_map,
                                               const float* __restrict__ lmda,
                                               float* __restrict__ out) {
    const int bc = (BC - 1) - blockIdx.x;   // reverse order for L2 tail reuse
    const int b_own = bc >> 6;
    const int c = bc & 63;
    const int tid = threadIdx.x;
    const int lane = tid & 31;
    const int wid = tid >> 5;

    __shared__ int   sh_cid[B_DIM];
    __shared__ float sh_ps1[B_DIM];
    __shared__ float sh_ps2[B_DIM];
    __shared__ float sh_r1[2], sh_r2[2], sh_rc[2];
    __shared__ float sh_scale, sh_bias;

    // ---- prologue stage 1: cid + this channel's partials (L2-hot) ----
    if (tid < B_DIM) {
        const float* row = cluster_map + tid * K_CL;
        float best = row[0];
        int bi = 0;
#pragma unroll
        for (int k = 1; k < K_CL; ++k) {
            float v = row[k];
            if (v > best) { best = v; bi = k; }
        }
        sh_cid[tid] = bi;
        sh_ps1[tid] = __ldcg(&g_s1[tid * C_DIM + c]);
        sh_ps2[tid] = __ldcg(&g_s2[tid * C_DIM + c]);
    }
    __syncthreads();

    // ---- prologue stage 2: predicated tree reduction over 64 samples ----
    if (tid < B_DIM) {
        const int kown = sh_cid[b_own];
        const float m = (sh_cid[tid] == kown) ? 1.0f : 0.0f;
        float v1 = m * sh_ps1[tid];
        float v2 = m * sh_ps2[tid];
        float vc = m;
#pragma unroll
        for (int off = 16; off > 0; off >>= 1) {
            v1 += __shfl_down_sync(0xffffffffu, v1, off);
            v2 += __shfl_down_sync(0xffffffffu, v2, off);
            vc += __shfl_down_sync(0xffffffffu, vc, off);
        }
        if (lane == 0) { sh_r1[wid] = v1; sh_r2[wid] = v2; sh_rc[wid] = vc; }
    }
    __syncthreads();

    if (tid == 0) {
        float cs1 = sh_r1[0] + sh_r1[1];
        float cs2 = sh_r2[0] + sh_r2[1];
        float cnt = sh_rc[0] + sh_rc[1];

        float n_k = fmaxf(cnt * (float)HW, 1.0f);
        float cmu = cs1 / n_k;
        float cvar = (cs2 - n_k * cmu * cmu) / fmaxf(n_k - 1.0f, 1.0f);
        float cstd = sqrtf(cvar + EPS);

        float smu = sh_ps1[b_own] * (1.0f / (float)HW);
        float svar = (sh_ps2[b_own] - (float)HW * smu * smu) * (1.0f / (float)(HW - 1));
        float sstd = sqrtf(svar + EPS);
        float l = lmda[b_own];
        float std_mix = sstd * l + cstd * (1.0f - l);
        float mu_mix = smu * l + cmu * (1.0f - l);
        float scale = std_mix / sstd;
        sh_scale = scale;
        sh_bias = mu_mix - smu * scale;
    }
    __syncthreads();

    const float scale = sh_scale;
    const float bias = sh_bias;

    // ---- stream: identical to the measured-58us apply loop ----
    const float4* __restrict__ px =
        reinterpret_cast<const float4*>(x + (size_t)bc * HW);
    float4* __restrict__ po = reinterpret_cast<float4*>(out + (size_t)bc * HW);

#pragma unroll 4
    for (int i = tid; i < HW4; i += 256) {
        float4 v = px[i];
        v.x = fmaf(v.x, scale, bias);
        v.y = fmaf(v.y, scale, bias);
        v.z = fmaf(v.z, scale, bias);
        v.w = fmaf(v.w, scale, bias);
        __stcs(&po[i], v);   // streaming store: don't pollute L2
    }
}

extern "C" void kernel_launch(void* const* d_in, const int* in_sizes, int n_in,
                              void* d_out, int out_size) {
    const float* x = (const float*)d_in[0];            // [64,64,112,112]
    const float* cluster_map = (const float*)d_in[1];  // [1,64,8]
    const float* lmda = (const float*)d_in[2];         // [64,1,1,1]
    float* out = (float*)d_out;

    k_moments<<<BC, 256>>>(x);
    k_apply<<<BC, 256>>>(x, cluster_map, lmda, out);
}